// round 13
// baseline (speedup 1.0000x reference)
#include <cuda_runtime.h>
#include <cuda_fp16.h>
#include <cstdint>
#include <cstddef>

#define BATCH 16384
#define HDIM  512
#define ODIM  128
#define NEXP  5
#define NZ    15

#define BM    128
#define BN    128
#define BK    64             // halfs per k-tile (128B rows)
#define NKT   (HDIM/BK)      // 8
#define STAGES 3
#define NTH   128            // 4 warps, warp tile 64x64
#define B_OFF 16384
#define STAGE_BYTES 32768    // 16KB A + 16KB B

// device scratch (static; allocation-guard-safe)
__device__ __half g_Xh [(size_t)3  * BATCH * HDIM];   // fp16 inputs  [bank][m][k]
__device__ __half g_H  [(size_t)NZ * BATCH * HDIM];   // fp16 hidden  [z][m][k]
__device__ __half g_W1h[(size_t)NZ * HDIM * HDIM];    // fp16 [z][n][k] (transposed)
__device__ __half g_W2h[(size_t)NZ * ODIM * HDIM];    // fp16 [z][n][k] (transposed)

// ---------------------------------------------------------------------------
// helpers
// ---------------------------------------------------------------------------
__device__ __forceinline__ uint32_t smem_u32(const void* p) {
    uint32_t a;
    asm("{ .reg .u64 t; cvta.to.shared.u64 t, %1; cvt.u32.u64 %0, t; }" : "=r"(a) : "l"(p));
    return a;
}
__device__ __forceinline__ void cp16(uint32_t s, const void* g) {
    asm volatile("cp.async.cg.shared.global [%0], [%1], 16;\n" :: "r"(s), "l"(g));
}
__device__ __forceinline__ void cp_commit() { asm volatile("cp.async.commit_group;\n"); }
template<int N> __device__ __forceinline__ void cp_wait() {
    asm volatile("cp.async.wait_group %0;\n" :: "n"(N));
}
__device__ __forceinline__ void ldsm4(uint32_t& d0, uint32_t& d1, uint32_t& d2, uint32_t& d3,
                                      uint32_t a) {
    asm volatile("ldmatrix.sync.aligned.m8n8.x4.shared.b16 {%0,%1,%2,%3}, [%4];"
                 : "=r"(d0), "=r"(d1), "=r"(d2), "=r"(d3) : "r"(a));
}
__device__ __forceinline__ void mma16816(float& d0, float& d1, float& d2, float& d3,
                                         uint32_t a0, uint32_t a1, uint32_t a2, uint32_t a3,
                                         uint32_t b0, uint32_t b1) {
    asm volatile(
        "mma.sync.aligned.m16n8k16.row.col.f32.f16.f16.f32 "
        "{%0,%1,%2,%3}, {%4,%5,%6,%7}, {%8,%9}, {%0,%1,%2,%3};"
        : "+f"(d0), "+f"(d1), "+f"(d2), "+f"(d3)
        : "r"(a0), "r"(a1), "r"(a2), "r"(a3), "r"(b0), "r"(b1));
}

// ---------------------------------------------------------------------------
// merged conversion kernel: one launch does X (fp32->fp16) and W (transpose+cvt)
// grid: [0, NXB) -> X part, [NXB, NXB+NWB) -> W part. 256 threads.
// ---------------------------------------------------------------------------
#define NX4  ((size_t)3 * BATCH * HDIM / 4)          // 6291456 float4s
#define NXB  ((int)((NX4 + 255) / 256))              // 24576 blocks
#define NWB  (NZ * 256 + NZ * 64)                    // 4800 blocks

__global__ void cvt_all_kernel(const float* __restrict__ x0, const float* __restrict__ x1,
                               const float* __restrict__ x2,
                               const float* __restrict__ sW1, const float* __restrict__ tW1,
                               const float* __restrict__ sW2, const float* __restrict__ tW2)
{
    if (blockIdx.x < NXB) {
        const size_t i = (size_t)blockIdx.x * 256 + threadIdx.x;
        if (i >= NX4) return;
        const size_t per = (size_t)BATCH * HDIM / 4;
        const int bank = (int)(i / per);
        const size_t r = i - (size_t)bank * per;
        const float4 v = ((const float4*)(bank == 0 ? x0 : bank == 1 ? x1 : x2))[r];
        __half2 h0 = __floats2half2_rn(v.x, v.y);
        __half2 h1 = __floats2half2_rn(v.z, v.w);
        ((uint2*)g_Xh)[i] = make_uint2(*(uint32_t*)&h0, *(uint32_t*)&h1);
        return;
    }

    __shared__ float t[32][33];
    int b = blockIdx.x - NXB;
    const float* src; __half* dst; int N, n0, k0;
    if (b < NZ * 256) {                      // W1
        const int z = b >> 8, r = b & 255;
        n0 = (r >> 4) * 32; k0 = (r & 15) * 32;
        src = (z < NEXP) ? sW1 + (size_t)z * HDIM * HDIM
                         : tW1 + (size_t)(z - NEXP) * HDIM * HDIM;
        dst = g_W1h + (size_t)z * HDIM * HDIM;
        N = HDIM;
    } else {                                 // W2
        b -= NZ * 256;
        const int z = b >> 6, r = b & 63;
        k0 = (r >> 2) * 32; n0 = (r & 3) * 32;
        src = (z < NEXP) ? sW2 + (size_t)z * HDIM * ODIM
                         : tW2 + (size_t)(z - NEXP) * HDIM * ODIM;
        dst = g_W2h + (size_t)z * ODIM * HDIM;
        N = ODIM;
    }
    const int tx = threadIdx.x & 31, ty = threadIdx.x >> 5;   // flatten (32,8)
    #pragma unroll
    for (int i = 0; i < 4; ++i)
        t[ty + i * 8][tx] = src[(size_t)(k0 + ty + i * 8) * N + n0 + tx];
    __syncthreads();
    #pragma unroll
    for (int i = 0; i < 4; ++i)
        dst[(size_t)(n0 + ty + i * 8) * HDIM + k0 + tx] = __float2half_rn(t[tx][ty + i * 8]);
}

// ---------------------------------------------------------------------------
// fp16 tensor-core GEMM body: C[128,128] tile, 4 warps, warp tile 64x64.
// Fully-unrolled 8-iteration k-loop: stage offsets and ldsm addresses fold
// to compile-time constants.
// ---------------------------------------------------------------------------
template<bool RELU, bool OUT_HALF, int LDC>
__device__ __forceinline__ void gemm_body(const __half* __restrict__ A,
                                          const __half* __restrict__ W,
                                          const float*  __restrict__ bias,
                                          void* __restrict__ Cout)
{
    __shared__ __align__(1024) char smem[STAGES * STAGE_BYTES];
    const uint32_t sb = smem_u32(smem);

    const int tid = threadIdx.x, lane = tid & 31, wid = tid >> 5;
    const int wm = wid >> 1, wn = wid & 1;               // warps 2m x 2n, tile 64x64
    const int bm = blockIdx.y * BM, bn = blockIdx.x * BN;

    // ---- cp.async mapping: 8 A + 8 B granules (16B) per thread per stage ----
    const __half* Ag[8]; const __half* Bg[8]; uint32_t sAo[8], sBo[8];
    #pragma unroll
    for (int i = 0; i < 8; ++i) {
        const int idx = i * NTH + tid;
        const int r = idx >> 3, c = idx & 7;
        Ag[i] = A + (size_t)(bm + r) * HDIM + c * 8;
        Bg[i] = W + (size_t)(bn + r) * HDIM + c * 8;
        const uint32_t o = (uint32_t)(r * 128 + ((c ^ (r & 7)) << 4));
        sAo[i] = o;
        sBo[i] = B_OFF + o;
    }

    // ---- fragment address tables (8-granule-row swizzle) ----
    const int ah = lane >> 4;            // A k-half select
    uint32_t art[4]; int arx[4];
    #pragma unroll
    for (int mi = 0; mi < 4; ++mi) {
        const int r = wm * 64 + mi * 16 + (lane & 15);
        art[mi] = (uint32_t)(r * 128); arx[mi] = r & 7;
    }
    const int bh = (lane >> 3) & 1;      // B k-half select
    uint32_t nrt[4]; int nrx[4];
    #pragma unroll
    for (int p = 0; p < 4; ++p) {
        const int r = wn * 64 + p * 16 + ((lane >> 4) << 3) + (lane & 7);
        nrt[p] = B_OFF + (uint32_t)(r * 128); nrx[p] = r & 7;
    }

    float acc[4][8][4] = {};

    // ---- prologue: fill 2 stages ----
    #pragma unroll
    for (int s = 0; s < STAGES - 1; ++s) {
        const int ko = s * BK;
        const uint32_t base = sb + s * STAGE_BYTES;
        #pragma unroll
        for (int i = 0; i < 8; ++i) { cp16(base + sAo[i], Ag[i] + ko); }
        #pragma unroll
        for (int i = 0; i < 8; ++i) { cp16(base + sBo[i], Bg[i] + ko); }
        cp_commit();
    }

    #pragma unroll
    for (int kt = 0; kt < NKT; ++kt) {
        cp_wait<STAGES - 2>();
        __syncthreads();

        if (kt + STAGES - 1 < NKT) {
            const int ko = (kt + STAGES - 1) * BK;
            const uint32_t base = sb + ((kt + STAGES - 1) % STAGES) * STAGE_BYTES;
            #pragma unroll
            for (int i = 0; i < 8; ++i) { cp16(base + sAo[i], Ag[i] + ko); }
            #pragma unroll
            for (int i = 0; i < 8; ++i) { cp16(base + sBo[i], Bg[i] + ko); }
        }
        cp_commit();

        const uint32_t stg = sb + (kt % STAGES) * STAGE_BYTES;
        #pragma unroll
        for (int k16 = 0; k16 < 4; ++k16) {
            const int ga = k16 * 2 + ah;
            const int gb = k16 * 2 + bh;
            uint32_t af[4][4], bf[8][2];
            #pragma unroll
            for (int mi = 0; mi < 4; ++mi)
                ldsm4(af[mi][0], af[mi][1], af[mi][2], af[mi][3],
                      stg + art[mi] + ((uint32_t)(ga ^ arx[mi]) << 4));
            #pragma unroll
            for (int p = 0; p < 4; ++p)
                ldsm4(bf[2 * p][0], bf[2 * p][1], bf[2 * p + 1][0], bf[2 * p + 1][1],
                      stg + nrt[p] + ((uint32_t)(gb ^ nrx[p]) << 4));
            #pragma unroll
            for (int mi = 0; mi < 4; ++mi)
                #pragma unroll
                for (int ni = 0; ni < 8; ++ni)
                    mma16816(acc[mi][ni][0], acc[mi][ni][1], acc[mi][ni][2], acc[mi][ni][3],
                             af[mi][0], af[mi][1], af[mi][2], af[mi][3],
                             bf[ni][0], bf[ni][1]);
        }
    }

    // ---- epilogue: bias (+relu), write ----
    const int g = lane >> 2, t = lane & 3;
    #pragma unroll
    for (int mi = 0; mi < 4; ++mi) {
        const int r0g = bm + wm * 64 + mi * 16 + g;
        const int r1g = r0g + 8;
        #pragma unroll
        for (int ni = 0; ni < 8; ++ni) {
            const int c0g = bn + wn * 64 + ni * 8 + t * 2;
            const float bv0 = bias[c0g], bv1 = bias[c0g + 1];
            float v00 = acc[mi][ni][0] + bv0;
            float v01 = acc[mi][ni][1] + bv1;
            float v10 = acc[mi][ni][2] + bv0;
            float v11 = acc[mi][ni][3] + bv1;
            if (RELU) {
                v00 = fmaxf(v00, 0.0f); v01 = fmaxf(v01, 0.0f);
                v10 = fmaxf(v10, 0.0f); v11 = fmaxf(v11, 0.0f);
            }
            if (OUT_HALF) {
                *(__half2*)&((__half*)Cout)[(size_t)r0g * LDC + c0g] = __floats2half2_rn(v00, v01);
                *(__half2*)&((__half*)Cout)[(size_t)r1g * LDC + c0g] = __floats2half2_rn(v10, v11);
            } else {
                *(float2*)&((float*)Cout)[(size_t)r0g * LDC + c0g] = make_float2(v00, v01);
                *(float2*)&((float*)Cout)[(size_t)r1g * LDC + c0g] = make_float2(v10, v11);
            }
        }
    }
}

// ---------------------------------------------------------------------------
// kernels
// ---------------------------------------------------------------------------
__global__ __launch_bounds__(NTH, 2)
void gemm1_kernel(const float* __restrict__ sb1, const float* __restrict__ tb1)
{
    const int z = blockIdx.z, bank = z / NEXP, e = z - bank * NEXP;
    const __half* A = g_Xh + (size_t)bank * BATCH * HDIM;
    const __half* W = g_W1h + (size_t)z * HDIM * HDIM;
    const float* bias = (bank == 0) ? sb1 + (size_t)e * HDIM
                                    : tb1 + ((size_t)(bank - 1) * NEXP + e) * HDIM;
    __half* C = g_H + (size_t)z * BATCH * HDIM;
    gemm_body<true, true, HDIM>(A, W, bias, C);
}

__global__ __launch_bounds__(NTH, 2)
void gemm2_kernel(const float* __restrict__ sb2, const float* __restrict__ tb2,
                  float* __restrict__ out)
{
    const int z = blockIdx.z, bank = z / NEXP, e = z - bank * NEXP;
    const __half* A = g_H + (size_t)z * BATCH * HDIM;
    const __half* W = g_W2h + (size_t)z * ODIM * HDIM;
    const float* bias = (bank == 0) ? sb2 + (size_t)e * ODIM
                                    : tb2 + ((size_t)(bank - 1) * NEXP + e) * ODIM;
    gemm_body<false, false, ODIM>(A, W, bias, out + (size_t)z * BATCH * ODIM);
}

// ---------------------------------------------------------------------------
// launch
// ---------------------------------------------------------------------------
extern "C" void kernel_launch(void* const* d_in, const int* in_sizes, int n_in,
                              void* d_out, int out_size)
{
    const float* share_x  = (const float*)d_in[0];
    const float* task_x0  = (const float*)d_in[1];
    const float* task_x1  = (const float*)d_in[2];
    const float* share_W1 = (const float*)d_in[3];
    const float* share_b1 = (const float*)d_in[4];
    const float* share_W2 = (const float*)d_in[5];
    const float* share_b2 = (const float*)d_in[6];
    const float* task_W1  = (const float*)d_in[7];
    const float* task_b1  = (const float*)d_in[8];
    const float* task_W2  = (const float*)d_in[9];
    const float* task_b2  = (const float*)d_in[10];
    float* out = (float*)d_out;

    // 1) single merged conversion launch (X cvt + W transpose/cvt)
    cvt_all_kernel<<<NXB + NWB, 256>>>(share_x, task_x0, task_x1,
                                       share_W1, task_W1, share_W2, task_W2);

    // 2) GEMMs (R10 configs, fully-unrolled k-loops)
    gemm1_kernel<<<dim3(HDIM / BN, BATCH / BM, NZ), NTH>>>(share_b1, task_b1);
    gemm2_kernel<<<dim3(ODIM / BN, BATCH / BM, NZ), NTH>>>(share_b2, task_b2, out);
}

// round 14
// speedup vs baseline: 1.3814x; 1.3814x over previous
#include <cuda_runtime.h>
#include <cuda_fp16.h>
#include <cstdint>
#include <cstddef>

#define BATCH 16384
#define HDIM  512
#define ODIM  128
#define NEXP  5
#define NZ    15

#define BM    128
#define BN    128
#define BK    64             // halfs per k-tile (128B rows)
#define NKT   (HDIM/BK)      // 8
#define STAGES 3
#define NTH   128            // 4 warps, warp tile 64x64
#define B_OFF 16384
#define STAGE_BYTES 32768    // 16KB A + 16KB B

// device scratch (static; allocation-guard-safe)
__device__ __half g_Xh [(size_t)3  * BATCH * HDIM];   // fp16 inputs  [bank][m][k]
__device__ __half g_H  [(size_t)NZ * BATCH * HDIM];   // fp16 hidden  [z][m][k]
__device__ __half g_W1h[(size_t)NZ * HDIM * HDIM];    // fp16 [z][n][k] (transposed)
__device__ __half g_W2h[(size_t)NZ * ODIM * HDIM];    // fp16 [z][n][k] (transposed)

// ---------------------------------------------------------------------------
// helpers
// ---------------------------------------------------------------------------
__device__ __forceinline__ uint32_t smem_u32(const void* p) {
    uint32_t a;
    asm("{ .reg .u64 t; cvta.to.shared.u64 t, %1; cvt.u32.u64 %0, t; }" : "=r"(a) : "l"(p));
    return a;
}
__device__ __forceinline__ void cp16(uint32_t s, const void* g) {
    asm volatile("cp.async.cg.shared.global [%0], [%1], 16;\n" :: "r"(s), "l"(g));
}
__device__ __forceinline__ void cp_commit() { asm volatile("cp.async.commit_group;\n"); }
template<int N> __device__ __forceinline__ void cp_wait() {
    asm volatile("cp.async.wait_group %0;\n" :: "n"(N));
}
__device__ __forceinline__ void ldsm4(uint32_t& d0, uint32_t& d1, uint32_t& d2, uint32_t& d3,
                                      uint32_t a) {
    asm volatile("ldmatrix.sync.aligned.m8n8.x4.shared.b16 {%0,%1,%2,%3}, [%4];"
                 : "=r"(d0), "=r"(d1), "=r"(d2), "=r"(d3) : "r"(a));
}
__device__ __forceinline__ void mma16816(float& d0, float& d1, float& d2, float& d3,
                                         uint32_t a0, uint32_t a1, uint32_t a2, uint32_t a3,
                                         uint32_t b0, uint32_t b1) {
    asm volatile(
        "mma.sync.aligned.m16n8k16.row.col.f32.f16.f16.f32 "
        "{%0,%1,%2,%3}, {%4,%5,%6,%7}, {%8,%9}, {%0,%1,%2,%3};"
        : "+f"(d0), "+f"(d1), "+f"(d2), "+f"(d3)
        : "r"(a0), "r"(a1), "r"(a2), "r"(a3), "r"(b0), "r"(b1));
}

// ---------------------------------------------------------------------------
// merged conversion kernel (validated in R13: 36.5us, DRAM-bound, correct):
// one launch does X (fp32->fp16) and W (transpose+cvt).
// ---------------------------------------------------------------------------
#define NX4  ((size_t)3 * BATCH * HDIM / 4)          // 6291456 float4s
#define NXB  ((int)((NX4 + 255) / 256))              // 24576 blocks
#define NWB  (NZ * 256 + NZ * 64)                    // 4800 blocks

__global__ void cvt_all_kernel(const float* __restrict__ x0, const float* __restrict__ x1,
                               const float* __restrict__ x2,
                               const float* __restrict__ sW1, const float* __restrict__ tW1,
                               const float* __restrict__ sW2, const float* __restrict__ tW2)
{
    if (blockIdx.x < NXB) {
        const size_t i = (size_t)blockIdx.x * 256 + threadIdx.x;
        if (i >= NX4) return;
        const size_t per = (size_t)BATCH * HDIM / 4;
        const int bank = (int)(i / per);
        const size_t r = i - (size_t)bank * per;
        const float4 v = ((const float4*)(bank == 0 ? x0 : bank == 1 ? x1 : x2))[r];
        __half2 h0 = __floats2half2_rn(v.x, v.y);
        __half2 h1 = __floats2half2_rn(v.z, v.w);
        ((uint2*)g_Xh)[i] = make_uint2(*(uint32_t*)&h0, *(uint32_t*)&h1);
        return;
    }

    __shared__ float t[32][33];
    int b = blockIdx.x - NXB;
    const float* src; __half* dst; int N, n0, k0;
    if (b < NZ * 256) {                      // W1
        const int z = b >> 8, r = b & 255;
        n0 = (r >> 4) * 32; k0 = (r & 15) * 32;
        src = (z < NEXP) ? sW1 + (size_t)z * HDIM * HDIM
                         : tW1 + (size_t)(z - NEXP) * HDIM * HDIM;
        dst = g_W1h + (size_t)z * HDIM * HDIM;
        N = HDIM;
    } else {                                 // W2
        b -= NZ * 256;
        const int z = b >> 6, r = b & 63;
        k0 = (r >> 2) * 32; n0 = (r & 3) * 32;
        src = (z < NEXP) ? sW2 + (size_t)z * HDIM * ODIM
                         : tW2 + (size_t)(z - NEXP) * HDIM * ODIM;
        dst = g_W2h + (size_t)z * ODIM * HDIM;
        N = ODIM;
    }
    const int tx = threadIdx.x & 31, ty = threadIdx.x >> 5;   // flatten (32,8)
    #pragma unroll
    for (int i = 0; i < 4; ++i)
        t[ty + i * 8][tx] = src[(size_t)(k0 + ty + i * 8) * N + n0 + tx];
    __syncthreads();
    #pragma unroll
    for (int i = 0; i < 4; ++i)
        dst[(size_t)(n0 + ty + i * 8) * HDIM + k0 + tx] = __float2half_rn(t[tx][ty + i * 8]);
}

// ---------------------------------------------------------------------------
// fp16 tensor-core GEMM body — EXACT R10 code (the measured optimum):
// C[128,128] tile, 4 warps, warp tile 64x64, 3-stage cp.async, unroll-1 k-loop.
// ---------------------------------------------------------------------------
template<bool RELU, bool OUT_HALF, int LDC>
__device__ __forceinline__ void gemm_body(const __half* __restrict__ A,
                                          const __half* __restrict__ W,
                                          const float*  __restrict__ bias,
                                          void* __restrict__ Cout)
{
    __shared__ __align__(1024) char smem[STAGES * STAGE_BYTES];
    const uint32_t sb = smem_u32(smem);

    const int tid = threadIdx.x, lane = tid & 31, wid = tid >> 5;
    const int wm = wid >> 1, wn = wid & 1;               // warps 2m x 2n, tile 64x64
    const int bm = blockIdx.y * BM, bn = blockIdx.x * BN;

    // ---- cp.async mapping: 8 A + 8 B granules (16B) per thread per stage ----
    const __half* Ag[8]; const __half* Bg[8]; uint32_t sAo[8], sBo[8];
    #pragma unroll
    for (int i = 0; i < 8; ++i) {
        const int idx = i * NTH + tid;
        const int r = idx >> 3, c = idx & 7;
        Ag[i] = A + (size_t)(bm + r) * HDIM + c * 8;
        Bg[i] = W + (size_t)(bn + r) * HDIM + c * 8;
        const uint32_t o = (uint32_t)(r * 128 + ((c ^ (r & 7)) << 4));
        sAo[i] = o;
        sBo[i] = B_OFF + o;
    }

    // ---- fragment address tables (8-granule-row swizzle) ----
    const int ah = lane >> 4;            // A k-half select
    uint32_t art[4]; int arx[4];
    #pragma unroll
    for (int mi = 0; mi < 4; ++mi) {
        const int r = wm * 64 + mi * 16 + (lane & 15);
        art[mi] = (uint32_t)(r * 128); arx[mi] = r & 7;
    }
    const int bh = (lane >> 3) & 1;      // B k-half select
    uint32_t nrt[4]; int nrx[4];
    #pragma unroll
    for (int p = 0; p < 4; ++p) {
        const int r = wn * 64 + p * 16 + ((lane >> 4) << 3) + (lane & 7);
        nrt[p] = B_OFF + (uint32_t)(r * 128); nrx[p] = r & 7;
    }

    float acc[4][8][4] = {};

    // ---- prologue: fill 2 stages ----
    #pragma unroll
    for (int s = 0; s < STAGES - 1; ++s) {
        const int ko = s * BK;
        const uint32_t base = sb + s * STAGE_BYTES;
        #pragma unroll
        for (int i = 0; i < 8; ++i) { cp16(base + sAo[i], Ag[i] + ko); }
        #pragma unroll
        for (int i = 0; i < 8; ++i) { cp16(base + sBo[i], Bg[i] + ko); }
        cp_commit();
    }

    #pragma unroll 1
    for (int kt = 0; kt < NKT; ++kt) {
        cp_wait<STAGES - 2>();
        __syncthreads();

        if (kt + STAGES - 1 < NKT) {
            const int ko = (kt + STAGES - 1) * BK;
            const uint32_t base = sb + ((kt + STAGES - 1) % STAGES) * STAGE_BYTES;
            #pragma unroll
            for (int i = 0; i < 8; ++i) { cp16(base + sAo[i], Ag[i] + ko); }
            #pragma unroll
            for (int i = 0; i < 8; ++i) { cp16(base + sBo[i], Bg[i] + ko); }
        }
        cp_commit();

        const uint32_t stg = sb + (kt % STAGES) * STAGE_BYTES;
        #pragma unroll
        for (int k16 = 0; k16 < 4; ++k16) {
            const int ga = k16 * 2 + ah;
            const int gb = k16 * 2 + bh;
            uint32_t af[4][4], bf[8][2];
            #pragma unroll
            for (int mi = 0; mi < 4; ++mi)
                ldsm4(af[mi][0], af[mi][1], af[mi][2], af[mi][3],
                      stg + art[mi] + ((uint32_t)(ga ^ arx[mi]) << 4));
            #pragma unroll
            for (int p = 0; p < 4; ++p)
                ldsm4(bf[2 * p][0], bf[2 * p][1], bf[2 * p + 1][0], bf[2 * p + 1][1],
                      stg + nrt[p] + ((uint32_t)(gb ^ nrx[p]) << 4));
            #pragma unroll
            for (int mi = 0; mi < 4; ++mi)
                #pragma unroll
                for (int ni = 0; ni < 8; ++ni)
                    mma16816(acc[mi][ni][0], acc[mi][ni][1], acc[mi][ni][2], acc[mi][ni][3],
                             af[mi][0], af[mi][1], af[mi][2], af[mi][3],
                             bf[ni][0], bf[ni][1]);
        }
    }

    // ---- epilogue: bias (+relu), write ----
    const int g = lane >> 2, t = lane & 3;
    #pragma unroll
    for (int mi = 0; mi < 4; ++mi) {
        const int r0g = bm + wm * 64 + mi * 16 + g;
        const int r1g = r0g + 8;
        #pragma unroll
        for (int ni = 0; ni < 8; ++ni) {
            const int c0g = bn + wn * 64 + ni * 8 + t * 2;
            const float bv0 = bias[c0g], bv1 = bias[c0g + 1];
            float v00 = acc[mi][ni][0] + bv0;
            float v01 = acc[mi][ni][1] + bv1;
            float v10 = acc[mi][ni][2] + bv0;
            float v11 = acc[mi][ni][3] + bv1;
            if (RELU) {
                v00 = fmaxf(v00, 0.0f); v01 = fmaxf(v01, 0.0f);
                v10 = fmaxf(v10, 0.0f); v11 = fmaxf(v11, 0.0f);
            }
            if (OUT_HALF) {
                *(__half2*)&((__half*)Cout)[(size_t)r0g * LDC + c0g] = __floats2half2_rn(v00, v01);
                *(__half2*)&((__half*)Cout)[(size_t)r1g * LDC + c0g] = __floats2half2_rn(v10, v11);
            } else {
                *(float2*)&((float*)Cout)[(size_t)r0g * LDC + c0g] = make_float2(v00, v01);
                *(float2*)&((float*)Cout)[(size_t)r1g * LDC + c0g] = make_float2(v10, v11);
            }
        }
    }
}

// ---------------------------------------------------------------------------
// kernels
// ---------------------------------------------------------------------------
__global__ __launch_bounds__(NTH, 2)
void gemm1_kernel(const float* __restrict__ sb1, const float* __restrict__ tb1)
{
    const int z = blockIdx.z, bank = z / NEXP, e = z - bank * NEXP;
    const __half* A = g_Xh + (size_t)bank * BATCH * HDIM;
    const __half* W = g_W1h + (size_t)z * HDIM * HDIM;
    const float* bias = (bank == 0) ? sb1 + (size_t)e * HDIM
                                    : tb1 + ((size_t)(bank - 1) * NEXP + e) * HDIM;
    __half* C = g_H + (size_t)z * BATCH * HDIM;
    gemm_body<true, true, HDIM>(A, W, bias, C);
}

__global__ __launch_bounds__(NTH, 2)
void gemm2_kernel(const float* __restrict__ sb2, const float* __restrict__ tb2,
                  float* __restrict__ out)
{
    const int z = blockIdx.z, bank = z / NEXP, e = z - bank * NEXP;
    const __half* A = g_H + (size_t)z * BATCH * HDIM;
    const __half* W = g_W2h + (size_t)z * ODIM * HDIM;
    const float* bias = (bank == 0) ? sb2 + (size_t)e * ODIM
                                    : tb2 + ((size_t)(bank - 1) * NEXP + e) * ODIM;
    gemm_body<false, false, ODIM>(A, W, bias, out + (size_t)z * BATCH * ODIM);
}

// ---------------------------------------------------------------------------
// launch
// ---------------------------------------------------------------------------
extern "C" void kernel_launch(void* const* d_in, const int* in_sizes, int n_in,
                              void* d_out, int out_size)
{
    const float* share_x  = (const float*)d_in[0];
    const float* task_x0  = (const float*)d_in[1];
    const float* task_x1  = (const float*)d_in[2];
    const float* share_W1 = (const float*)d_in[3];
    const float* share_b1 = (const float*)d_in[4];
    const float* share_W2 = (const float*)d_in[5];
    const float* share_b2 = (const float*)d_in[6];
    const float* task_W1  = (const float*)d_in[7];
    const float* task_b1  = (const float*)d_in[8];
    const float* task_W2  = (const float*)d_in[9];
    const float* task_b2  = (const float*)d_in[10];
    float* out = (float*)d_out;

    // 1) single merged conversion launch (X cvt + W transpose/cvt)
    cvt_all_kernel<<<NXB + NWB, 256>>>(share_x, task_x0, task_x1,
                                       share_W1, task_W1, share_W2, task_W2);

    // 2) GEMMs — exact R10 code/config
    gemm1_kernel<<<dim3(HDIM / BN, BATCH / BM, NZ), NTH>>>(share_b1, task_b1);
    gemm2_kernel<<<dim3(ODIM / BN, BATCH / BM, NZ), NTH>>>(share_b2, task_b2, out);
}

// round 15
// speedup vs baseline: 1.3925x; 1.0080x over previous
#include <cuda_runtime.h>
#include <cuda_fp16.h>
#include <cstdint>
#include <cstddef>

#define BATCH 16384
#define HDIM  512
#define ODIM  128
#define NEXP  5
#define NZ    15

#define BM    128
#define BN    128
#define BK    64             // halfs per k-tile (128B rows)
#define NKT   (HDIM/BK)      // 8
#define STAGES 3
#define NTH   128            // 4 warps, warp tile 64x64
#define B_OFF 16384
#define STAGE_BYTES 32768    // 16KB A + 16KB B

// device scratch (static; allocation-guard-safe)
__device__ __half g_Xh [(size_t)3  * BATCH * HDIM];   // fp16 inputs  [bank][m][k]
__device__ __half g_H  [(size_t)NZ * BATCH * HDIM];   // fp16 hidden  [z][m][k]
__device__ __half g_W1h[(size_t)NZ * HDIM * HDIM];    // fp16 [z][n][k] (transposed)
__device__ __half g_W2h[(size_t)NZ * ODIM * HDIM];    // fp16 [z][n][k] (transposed)

// ---------------------------------------------------------------------------
// helpers
// ---------------------------------------------------------------------------
__device__ __forceinline__ uint32_t smem_u32(const void* p) {
    uint32_t a;
    asm("{ .reg .u64 t; cvta.to.shared.u64 t, %1; cvt.u32.u64 %0, t; }" : "=r"(a) : "l"(p));
    return a;
}
__device__ __forceinline__ void cp16(uint32_t s, const void* g) {
    asm volatile("cp.async.cg.shared.global [%0], [%1], 16;\n" :: "r"(s), "l"(g));
}
__device__ __forceinline__ void cp_commit() { asm volatile("cp.async.commit_group;\n"); }
template<int N> __device__ __forceinline__ void cp_wait() {
    asm volatile("cp.async.wait_group %0;\n" :: "n"(N));
}
__device__ __forceinline__ void ldsm4(uint32_t& d0, uint32_t& d1, uint32_t& d2, uint32_t& d3,
                                      uint32_t a) {
    asm volatile("ldmatrix.sync.aligned.m8n8.x4.shared.b16 {%0,%1,%2,%3}, [%4];"
                 : "=r"(d0), "=r"(d1), "=r"(d2), "=r"(d3) : "r"(a));
}
__device__ __forceinline__ void mma16816(float& d0, float& d1, float& d2, float& d3,
                                         uint32_t a0, uint32_t a1, uint32_t a2, uint32_t a3,
                                         uint32_t b0, uint32_t b1) {
    asm volatile(
        "mma.sync.aligned.m16n8k16.row.col.f32.f16.f16.f32 "
        "{%0,%1,%2,%3}, {%4,%5,%6,%7}, {%8,%9}, {%0,%1,%2,%3};"
        : "+f"(d0), "+f"(d1), "+f"(d2), "+f"(d3)
        : "r"(a0), "r"(a1), "r"(a2), "r"(a3), "r"(b0), "r"(b1));
}

// ---------------------------------------------------------------------------
// merged conversion kernel: X part now 2 independent float4s per thread
// (MLP=2, half the blocks); W part unchanged.
// ---------------------------------------------------------------------------
#define NX4  ((size_t)3 * BATCH * HDIM / 4)          // 6291456 float4s
#define NX8  (NX4 / 2)                               // 3145728 pairs
#define NXB  ((int)((NX8 + 255) / 256))              // 12288 blocks
#define NWB  (NZ * 256 + NZ * 64)                    // 4800 blocks

__global__ void cvt_all_kernel(const float* __restrict__ x0, const float* __restrict__ x1,
                               const float* __restrict__ x2,
                               const float* __restrict__ sW1, const float* __restrict__ tW1,
                               const float* __restrict__ sW2, const float* __restrict__ tW2)
{
    if (blockIdx.x < NXB) {
        const size_t p = (size_t)blockIdx.x * 256 + threadIdx.x;   // pair index
        if (p >= NX8) return;
        const size_t per = (size_t)BATCH * HDIM / 4;               // float4s per bank (even)
        const size_t i0 = p * 2;                                   // both float4s same bank
        const int bank = (int)(i0 / per);
        const size_t r0 = i0 - (size_t)bank * per;
        const float4* src = (const float4*)(bank == 0 ? x0 : bank == 1 ? x1 : x2);
        const float4 v0 = src[r0];
        const float4 v1 = src[r0 + 1];
        __half2 a0 = __floats2half2_rn(v0.x, v0.y);
        __half2 a1 = __floats2half2_rn(v0.z, v0.w);
        __half2 a2 = __floats2half2_rn(v1.x, v1.y);
        __half2 a3 = __floats2half2_rn(v1.z, v1.w);
        ((uint4*)g_Xh)[p] = make_uint4(*(uint32_t*)&a0, *(uint32_t*)&a1,
                                       *(uint32_t*)&a2, *(uint32_t*)&a3);
        return;
    }

    __shared__ float t[32][33];
    int b = blockIdx.x - NXB;
    const float* src; __half* dst; int N, n0, k0;
    if (b < NZ * 256) {                      // W1
        const int z = b >> 8, r = b & 255;
        n0 = (r >> 4) * 32; k0 = (r & 15) * 32;
        src = (z < NEXP) ? sW1 + (size_t)z * HDIM * HDIM
                         : tW1 + (size_t)(z - NEXP) * HDIM * HDIM;
        dst = g_W1h + (size_t)z * HDIM * HDIM;
        N = HDIM;
    } else {                                 // W2
        b -= NZ * 256;
        const int z = b >> 6, r = b & 63;
        k0 = (r >> 2) * 32; n0 = (r & 3) * 32;
        src = (z < NEXP) ? sW2 + (size_t)z * HDIM * ODIM
                         : tW2 + (size_t)(z - NEXP) * HDIM * ODIM;
        dst = g_W2h + (size_t)z * ODIM * HDIM;
        N = ODIM;
    }
    const int tx = threadIdx.x & 31, ty = threadIdx.x >> 5;   // flatten (32,8)
    #pragma unroll
    for (int i = 0; i < 4; ++i)
        t[ty + i * 8][tx] = src[(size_t)(k0 + ty + i * 8) * N + n0 + tx];
    __syncthreads();
    #pragma unroll
    for (int i = 0; i < 4; ++i)
        dst[(size_t)(n0 + ty + i * 8) * HDIM + k0 + tx] = __float2half_rn(t[tx][ty + i * 8]);
}

// ---------------------------------------------------------------------------
// fp16 tensor-core GEMM body — EXACT R10/R14 code (the measured optimum):
// C[128,128] tile, 4 warps, warp tile 64x64, 3-stage cp.async, unroll-1 k-loop.
// ---------------------------------------------------------------------------
template<bool RELU, bool OUT_HALF, int LDC>
__device__ __forceinline__ void gemm_body(const __half* __restrict__ A,
                                          const __half* __restrict__ W,
                                          const float*  __restrict__ bias,
                                          void* __restrict__ Cout)
{
    __shared__ __align__(1024) char smem[STAGES * STAGE_BYTES];
    const uint32_t sb = smem_u32(smem);

    const int tid = threadIdx.x, lane = tid & 31, wid = tid >> 5;
    const int wm = wid >> 1, wn = wid & 1;               // warps 2m x 2n, tile 64x64
    const int bm = blockIdx.y * BM, bn = blockIdx.x * BN;

    // ---- cp.async mapping: 8 A + 8 B granules (16B) per thread per stage ----
    const __half* Ag[8]; const __half* Bg[8]; uint32_t sAo[8], sBo[8];
    #pragma unroll
    for (int i = 0; i < 8; ++i) {
        const int idx = i * NTH + tid;
        const int r = idx >> 3, c = idx & 7;
        Ag[i] = A + (size_t)(bm + r) * HDIM + c * 8;
        Bg[i] = W + (size_t)(bn + r) * HDIM + c * 8;
        const uint32_t o = (uint32_t)(r * 128 + ((c ^ (r & 7)) << 4));
        sAo[i] = o;
        sBo[i] = B_OFF + o;
    }

    // ---- fragment address tables (8-granule-row swizzle) ----
    const int ah = lane >> 4;            // A k-half select
    uint32_t art[4]; int arx[4];
    #pragma unroll
    for (int mi = 0; mi < 4; ++mi) {
        const int r = wm * 64 + mi * 16 + (lane & 15);
        art[mi] = (uint32_t)(r * 128); arx[mi] = r & 7;
    }
    const int bh = (lane >> 3) & 1;      // B k-half select
    uint32_t nrt[4]; int nrx[4];
    #pragma unroll
    for (int p = 0; p < 4; ++p) {
        const int r = wn * 64 + p * 16 + ((lane >> 4) << 3) + (lane & 7);
        nrt[p] = B_OFF + (uint32_t)(r * 128); nrx[p] = r & 7;
    }

    float acc[4][8][4] = {};

    // ---- prologue: fill 2 stages ----
    #pragma unroll
    for (int s = 0; s < STAGES - 1; ++s) {
        const int ko = s * BK;
        const uint32_t base = sb + s * STAGE_BYTES;
        #pragma unroll
        for (int i = 0; i < 8; ++i) { cp16(base + sAo[i], Ag[i] + ko); }
        #pragma unroll
        for (int i = 0; i < 8; ++i) { cp16(base + sBo[i], Bg[i] + ko); }
        cp_commit();
    }

    #pragma unroll 1
    for (int kt = 0; kt < NKT; ++kt) {
        cp_wait<STAGES - 2>();
        __syncthreads();

        if (kt + STAGES - 1 < NKT) {
            const int ko = (kt + STAGES - 1) * BK;
            const uint32_t base = sb + ((kt + STAGES - 1) % STAGES) * STAGE_BYTES;
            #pragma unroll
            for (int i = 0; i < 8; ++i) { cp16(base + sAo[i], Ag[i] + ko); }
            #pragma unroll
            for (int i = 0; i < 8; ++i) { cp16(base + sBo[i], Bg[i] + ko); }
        }
        cp_commit();

        const uint32_t stg = sb + (kt % STAGES) * STAGE_BYTES;
        #pragma unroll
        for (int k16 = 0; k16 < 4; ++k16) {
            const int ga = k16 * 2 + ah;
            const int gb = k16 * 2 + bh;
            uint32_t af[4][4], bf[8][2];
            #pragma unroll
            for (int mi = 0; mi < 4; ++mi)
                ldsm4(af[mi][0], af[mi][1], af[mi][2], af[mi][3],
                      stg + art[mi] + ((uint32_t)(ga ^ arx[mi]) << 4));
            #pragma unroll
            for (int p = 0; p < 4; ++p)
                ldsm4(bf[2 * p][0], bf[2 * p][1], bf[2 * p + 1][0], bf[2 * p + 1][1],
                      stg + nrt[p] + ((uint32_t)(gb ^ nrx[p]) << 4));
            #pragma unroll
            for (int mi = 0; mi < 4; ++mi)
                #pragma unroll
                for (int ni = 0; ni < 8; ++ni)
                    mma16816(acc[mi][ni][0], acc[mi][ni][1], acc[mi][ni][2], acc[mi][ni][3],
                             af[mi][0], af[mi][1], af[mi][2], af[mi][3],
                             bf[ni][0], bf[ni][1]);
        }
    }

    // ---- epilogue: bias (+relu), write ----
    const int g = lane >> 2, t = lane & 3;
    #pragma unroll
    for (int mi = 0; mi < 4; ++mi) {
        const int r0g = bm + wm * 64 + mi * 16 + g;
        const int r1g = r0g + 8;
        #pragma unroll
        for (int ni = 0; ni < 8; ++ni) {
            const int c0g = bn + wn * 64 + ni * 8 + t * 2;
            const float bv0 = bias[c0g], bv1 = bias[c0g + 1];
            float v00 = acc[mi][ni][0] + bv0;
            float v01 = acc[mi][ni][1] + bv1;
            float v10 = acc[mi][ni][2] + bv0;
            float v11 = acc[mi][ni][3] + bv1;
            if (RELU) {
                v00 = fmaxf(v00, 0.0f); v01 = fmaxf(v01, 0.0f);
                v10 = fmaxf(v10, 0.0f); v11 = fmaxf(v11, 0.0f);
            }
            if (OUT_HALF) {
                *(__half2*)&((__half*)Cout)[(size_t)r0g * LDC + c0g] = __floats2half2_rn(v00, v01);
                *(__half2*)&((__half*)Cout)[(size_t)r1g * LDC + c0g] = __floats2half2_rn(v10, v11);
            } else {
                *(float2*)&((float*)Cout)[(size_t)r0g * LDC + c0g] = make_float2(v00, v01);
                *(float2*)&((float*)Cout)[(size_t)r1g * LDC + c0g] = make_float2(v10, v11);
            }
        }
    }
}

// ---------------------------------------------------------------------------
// kernels
// ---------------------------------------------------------------------------
__global__ __launch_bounds__(NTH, 2)
void gemm1_kernel(const float* __restrict__ sb1, const float* __restrict__ tb1)
{
    const int z = blockIdx.z, bank = z / NEXP, e = z - bank * NEXP;
    const __half* A = g_Xh + (size_t)bank * BATCH * HDIM;
    const __half* W = g_W1h + (size_t)z * HDIM * HDIM;
    const float* bias = (bank == 0) ? sb1 + (size_t)e * HDIM
                                    : tb1 + ((size_t)(bank - 1) * NEXP + e) * HDIM;
    __half* C = g_H + (size_t)z * BATCH * HDIM;
    gemm_body<true, true, HDIM>(A, W, bias, C);
}

__global__ __launch_bounds__(NTH, 2)
void gemm2_kernel(const float* __restrict__ sb2, const float* __restrict__ tb2,
                  float* __restrict__ out)
{
    const int z = blockIdx.z, bank = z / NEXP, e = z - bank * NEXP;
    const __half* A = g_H + (size_t)z * BATCH * HDIM;
    const __half* W = g_W2h + (size_t)z * ODIM * HDIM;
    const float* bias = (bank == 0) ? sb2 + (size_t)e * ODIM
                                    : tb2 + ((size_t)(bank - 1) * NEXP + e) * ODIM;
    gemm_body<false, false, ODIM>(A, W, bias, out + (size_t)z * BATCH * ODIM);
}

// ---------------------------------------------------------------------------
// launch
// ---------------------------------------------------------------------------
extern "C" void kernel_launch(void* const* d_in, const int* in_sizes, int n_in,
                              void* d_out, int out_size)
{
    const float* share_x  = (const float*)d_in[0];
    const float* task_x0  = (const float*)d_in[1];
    const float* task_x1  = (const float*)d_in[2];
    const float* share_W1 = (const float*)d_in[3];
    const float* share_b1 = (const float*)d_in[4];
    const float* share_W2 = (const float*)d_in[5];
    const float* share_b2 = (const float*)d_in[6];
    const float* task_W1  = (const float*)d_in[7];
    const float* task_b1  = (const float*)d_in[8];
    const float* task_W2  = (const float*)d_in[9];
    const float* task_b2  = (const float*)d_in[10];
    float* out = (float*)d_out;

    // 1) single merged conversion launch (X cvt MLP=2 + W transpose/cvt)
    cvt_all_kernel<<<NXB + NWB, 256>>>(share_x, task_x0, task_x1,
                                       share_W1, task_W1, share_W2, task_W2);

    // 2) GEMMs — exact R10/R14 code/config (frozen optimum)
    gemm1_kernel<<<dim3(HDIM / BN, BATCH / BM, NZ), NTH>>>(share_b1, task_b1);
    gemm2_kernel<<<dim3(ODIM / BN, BATCH / BM, NZ), NTH>>>(share_b2, task_b2, out);
}